// round 4
// baseline (speedup 1.0000x reference)
#include <cuda_runtime.h>
#include <cuda_bf16.h>
#include <cstdint>

#define MAX_N 50000
#define MAX_E 800000
#define D 128

// Scratch in device globals (no allocation allowed). 16B-aligned: accessed as float4.
__device__ int   g_is64;
__device__ int   g_deg[MAX_N];
__device__ int   g_off[MAX_N + 1];
__device__ int   g_cursor[MAX_N];
__device__ int   g_esrc[MAX_E];
__device__ __align__(16) float g_agg[(size_t)MAX_N * D];
__device__ __align__(16) float g_h[(size_t)MAX_N * D];

// ---------------------------------------------------------------------------
// Edge-index dtype detection: dataset declares int64 but JAX default config
// emits int32. If int64 with values < 2^31, every odd int32 word is zero.
// ---------------------------------------------------------------------------
__global__ void k_detect(const int* __restrict__ ei32) {
    if (blockIdx.x == 0 && threadIdx.x == 0) {
        int allzero = 1;
        #pragma unroll
        for (int i = 1; i < 64; i += 2)
            if (ei32[i] != 0) allzero = 0;
        g_is64 = allzero;
    }
}

__device__ __forceinline__ int edge_at(const void* ei, int idx, int is64) {
    return is64 ? (int)((const long long*)ei)[idx] : ((const int*)ei)[idx];
}

// ---------------------------------------------------------------------------
// CSR build
// ---------------------------------------------------------------------------
__global__ void k_zero_deg(int n) {
    int i = blockIdx.x * blockDim.x + threadIdx.x;
    if (i < n) g_deg[i] = 0;
}

__global__ void k_hist(const void* __restrict__ ei, int E) {
    int e = blockIdx.x * blockDim.x + threadIdx.x;
    int is64 = g_is64;
    if (e < E) {
        int d = edge_at(ei, E + e, is64);
        atomicAdd(&g_deg[d], 1);
    }
}

// Single-block exclusive scan over n counters
__global__ void k_scan(int n) {
    __shared__ int warp_sums[32];
    __shared__ int carry_s;
    if (threadIdx.x == 0) carry_s = 0;
    __syncthreads();
    int lane = threadIdx.x & 31, wid = threadIdx.x >> 5;
    for (int base = 0; base < n; base += 1024) {
        int i = base + threadIdx.x;
        int v = (i < n) ? g_deg[i] : 0;
        int s = v;
        #pragma unroll
        for (int o = 1; o < 32; o <<= 1) {
            int t = __shfl_up_sync(0xFFFFFFFFu, s, o);
            if (lane >= o) s += t;
        }
        if (lane == 31) warp_sums[wid] = s;
        __syncthreads();
        if (wid == 0) {
            int ws = warp_sums[lane];
            #pragma unroll
            for (int o = 1; o < 32; o <<= 1) {
                int t = __shfl_up_sync(0xFFFFFFFFu, ws, o);
                if (lane >= o) ws += t;
            }
            warp_sums[lane] = ws;
        }
        __syncthreads();
        int warp_off = (wid > 0) ? warp_sums[wid - 1] : 0;
        int incl = s + warp_off;
        int excl = incl - v + carry_s;
        if (i < n) { g_off[i] = excl; g_cursor[i] = excl; }
        __syncthreads();
        if (threadIdx.x == 1023) carry_s += incl;
        __syncthreads();
    }
    if (threadIdx.x == 0) g_off[n] = carry_s;
}

__global__ void k_fill(const void* __restrict__ ei, int E) {
    int e = blockIdx.x * blockDim.x + threadIdx.x;
    int is64 = g_is64;
    if (e < E) {
        int s = edge_at(ei, e, is64);
        int d = edge_at(ei, E + e, is64);
        int p = atomicAdd(&g_cursor[d], 1);
        g_esrc[p] = s;
    }
}

// ---------------------------------------------------------------------------
// Aggregation: warp per node, mean over in-neighbors. Writes g_agg.
// ---------------------------------------------------------------------------
__global__ void k_aggregate(const float* __restrict__ xext, int use_h, int n) {
    const float* xin = use_h ? (const float*)g_h : xext;
    int warp = (blockIdx.x * blockDim.x + threadIdx.x) >> 5;
    int lane = threadIdx.x & 31;
    if (warp >= n) return;
    int s0 = g_off[warp];
    int s1 = g_off[warp + 1];
    float4 acc = make_float4(0.f, 0.f, 0.f, 0.f);
    for (int e = s0; e < s1; e++) {
        int src = g_esrc[e];
        float4 v = *(const float4*)(xin + (size_t)src * D + lane * 4);
        acc.x += v.x; acc.y += v.y; acc.z += v.z; acc.w += v.w;
    }
    int cnt = s1 - s0;
    float inv = (cnt > 0) ? (1.0f / (float)cnt) : 0.0f;
    acc.x *= inv; acc.y *= inv; acc.z *= inv; acc.w *= inv;
    *(float4*)(g_agg + (size_t)warp * D + lane * 4) = acc;
}

// ---------------------------------------------------------------------------
// Fused GEMM: out = [relu]( g_agg @ Wl^T + bias + B @ Wr^T )
// Static shared (~45.5KB): As[56][128] input tile, Ws[32][132] transposed
// weight chunk. Stride 132 is a multiple of 4 -> all float4 LDS 16B-aligned;
// the 4-bank skew per k-row keeps transposed stores conflict-free.
// 256 threads; tx=tid&31 -> 4 cols, ty=tid>>5 -> 7 rows. acc[7][4].
// ---------------------------------------------------------------------------
#define M_TILE 56
#define WSTR 132

template <bool RELU>
__global__ void __launch_bounds__(256)
k_gemm_fused(const float* __restrict__ Bext, int B_is_h,
             const float* __restrict__ Wl, const float* __restrict__ Wr,
             const float* __restrict__ bias,
             float* __restrict__ outext, int out_is_h, int n) {
    __shared__ __align__(16) float As[M_TILE * 128];
    __shared__ __align__(16) float Ws[32 * WSTR];

    const float* Bp = B_is_h ? (const float*)g_h : Bext;
    float* outp = out_is_h ? (float*)g_h : outext;

    const int tid = threadIdx.x;
    const int tx = tid & 31;          // cols tx*4 .. tx*4+3
    const int ty = tid >> 5;          // rows ty*7 .. ty*7+6
    const int row0 = blockIdx.x * M_TILE;

    float acc[7][4];
    #pragma unroll
    for (int i = 0; i < 7; i++)
        #pragma unroll
        for (int c = 0; c < 4; c++) acc[i][c] = 0.f;

    // Ws load indexing: 32 j-rows per iter x4 iters, 8 k-quads per j
    const int wj  = tid >> 3;         // 0..31
    const int wkk = tid & 7;          // 0..7

    #pragma unroll
    for (int pass = 0; pass < 2; pass++) {
        const float* W = pass ? Wr : Wl;
        const float* X = pass ? Bp : (const float*)g_agg;

        __syncthreads();   // previous compute fully done before overwriting As/Ws
        // Load As: 56x128 tile, coalesced float4
        #pragma unroll
        for (int it = 0; it < 7; it++) {
            int idx = it * 256 + tid;          // 0..1791
            int r = idx >> 5, c = idx & 31;
            int gr = row0 + r;
            float4 v = make_float4(0.f, 0.f, 0.f, 0.f);
            if (gr < n) v = *(const float4*)(X + (size_t)gr * D + c * 4);
            *(float4*)&As[r * 128 + c * 4] = v;
        }

        for (int kc = 0; kc < 128; kc += 32) {
            if (kc > 0) __syncthreads();       // compute(prev chunk) done
            // Load Ws chunk transposed: Ws[k*WSTR + j] = W[j*128 + kc + k]
            #pragma unroll
            for (int it = 0; it < 4; it++) {
                int j = it * 32 + wj;          // 0..127
                float4 v = *(const float4*)(W + j * 128 + kc + wkk * 4);
                Ws[(wkk * 4 + 0) * WSTR + j] = v.x;
                Ws[(wkk * 4 + 1) * WSTR + j] = v.y;
                Ws[(wkk * 4 + 2) * WSTR + j] = v.z;
                Ws[(wkk * 4 + 3) * WSTR + j] = v.w;
            }
            __syncthreads();

            #pragma unroll 4
            for (int k = 0; k < 32; k += 4) {
                float4 wv0 = *(const float4*)&Ws[(k + 0) * WSTR + tx * 4];
                float4 wv1 = *(const float4*)&Ws[(k + 1) * WSTR + tx * 4];
                float4 wv2 = *(const float4*)&Ws[(k + 2) * WSTR + tx * 4];
                float4 wv3 = *(const float4*)&Ws[(k + 3) * WSTR + tx * 4];
                #pragma unroll
                for (int i = 0; i < 7; i++) {
                    float4 av = *(const float4*)&As[(ty * 7 + i) * 128 + kc + k];
                    acc[i][0] += av.x * wv0.x; acc[i][1] += av.x * wv0.y;
                    acc[i][2] += av.x * wv0.z; acc[i][3] += av.x * wv0.w;
                    acc[i][0] += av.y * wv1.x; acc[i][1] += av.y * wv1.y;
                    acc[i][2] += av.y * wv1.z; acc[i][3] += av.y * wv1.w;
                    acc[i][0] += av.z * wv2.x; acc[i][1] += av.z * wv2.y;
                    acc[i][2] += av.z * wv2.z; acc[i][3] += av.z * wv2.w;
                    acc[i][0] += av.w * wv3.x; acc[i][1] += av.w * wv3.y;
                    acc[i][2] += av.w * wv3.z; acc[i][3] += av.w * wv3.w;
                }
            }
        }
    }

    float4 bb = *(const float4*)&bias[tx * 4];
    #pragma unroll
    for (int i = 0; i < 7; i++) {
        int gr = row0 + ty * 7 + i;
        if (gr < n) {
            float4 v;
            v.x = acc[i][0] + bb.x;
            v.y = acc[i][1] + bb.y;
            v.z = acc[i][2] + bb.z;
            v.w = acc[i][3] + bb.w;
            if (RELU) {
                v.x = fmaxf(v.x, 0.f); v.y = fmaxf(v.y, 0.f);
                v.z = fmaxf(v.z, 0.f); v.w = fmaxf(v.w, 0.f);
            }
            *(float4*)(outp + (size_t)gr * D + tx * 4) = v;
        }
    }
}

// ---------------------------------------------------------------------------
extern "C" void kernel_launch(void* const* d_in, const int* in_sizes, int n_in,
                              void* d_out, int out_size) {
    const float* x   = (const float*)d_in[0];
    const void*  ei  = d_in[1];
    const float* Wl0 = (const float*)d_in[2];
    const float* bl0 = (const float*)d_in[3];
    const float* Wr0 = (const float*)d_in[4];
    const float* Wl1 = (const float*)d_in[5];
    const float* bl1 = (const float*)d_in[6];
    const float* Wr1 = (const float*)d_in[7];
    float*       out = (float*)d_out;

    const int n = in_sizes[0] / D;
    const int E = in_sizes[1] / 2;

    // CSR build (graph identical for both layers)
    k_detect<<<1, 32>>>((const int*)ei);
    k_zero_deg<<<(n + 255) / 256, 256>>>(n);
    k_hist<<<(E + 255) / 256, 256>>>(ei, E);
    k_scan<<<1, 1024>>>(n);
    k_fill<<<(E + 255) / 256, 256>>>(ei, E);

    const int agg_blocks  = (n * 32 + 255) / 256;
    const int gemm_blocks = (n + M_TILE - 1) / M_TILE;

    // Layer 0: g_h = relu(agg(x) @ Wl0^T + b0 + x @ Wr0^T)
    k_aggregate<<<agg_blocks, 256>>>(x, /*use_h=*/0, n);
    k_gemm_fused<true><<<gemm_blocks, 256>>>(x, /*B_is_h=*/0, Wl0, Wr0, bl0,
                                             nullptr, /*out_is_h=*/1, n);

    // Layer 1: out = agg(g_h) @ Wl1^T + b1 + g_h @ Wr1^T
    k_aggregate<<<agg_blocks, 256>>>(nullptr, /*use_h=*/1, n);
    k_gemm_fused<false><<<gemm_blocks, 256>>>(nullptr, /*B_is_h=*/1, Wl1, Wr1, bl1,
                                              out, /*out_is_h=*/0, n);
}

// round 6
// speedup vs baseline: 1.7127x; 1.7127x over previous
#include <cuda_runtime.h>
#include <cuda_bf16.h>
#include <cstdint>

#define MAX_N 50000
#define MAX_E 800000
#define D 128

// Scratch in device globals. 16B-aligned where accessed as float4.
__device__ int   g_is64;
__device__ int   g_deg[MAX_N];
__device__ int   g_off[MAX_N + 1];
__device__ int   g_cursor[MAX_N];
__device__ int   g_esrc[MAX_E];
__device__ int   g_bsum[64];
__device__ int   g_bpre[64];
__device__ __align__(16) float g_agg[(size_t)MAX_N * D];
__device__ __align__(16) float g_h[(size_t)MAX_N * D];

// ---------------------------------------------------------------------------
// sm_80-compatible tensor-core primitives (NO tcgen05: harness targets sm_103
// without the 'a' feature set, so only base-ISA instructions are available).
// ---------------------------------------------------------------------------
__device__ __forceinline__ uint32_t smem_u32(const void* p) {
    uint32_t a;
    asm("{ .reg .u64 t; cvta.to.shared.u64 t, %1; cvt.u32.u64 %0, t; }" : "=r"(a) : "l"(p));
    return a;
}

#define LDSM_X4(r0, r1, r2, r3, addr) \
    asm volatile("ldmatrix.sync.aligned.m8n8.x4.shared.b16 {%0,%1,%2,%3}, [%4];" \
                 : "=r"(r0), "=r"(r1), "=r"(r2), "=r"(r3) : "r"(addr))

#define MMA16816(c, a, b0, b1) \
    asm volatile("mma.sync.aligned.m16n8k16.row.col.f32.bf16.bf16.f32 " \
                 "{%0,%1,%2,%3}, {%4,%5,%6,%7}, {%8,%9}, {%0,%1,%2,%3};" \
                 : "+f"((c)[0]), "+f"((c)[1]), "+f"((c)[2]), "+f"((c)[3]) \
                 : "r"((a)[0]), "r"((a)[1]), "r"((a)[2]), "r"((a)[3]), \
                   "r"(b0), "r"(b1))

// ---------------------------------------------------------------------------
// Edge-index dtype detection (dataset says int64; JAX default emits int32)
// ---------------------------------------------------------------------------
__global__ void k_detect(const int* __restrict__ ei32) {
    if (blockIdx.x == 0 && threadIdx.x == 0) {
        int allzero = 1;
        #pragma unroll
        for (int i = 1; i < 64; i += 2)
            if (ei32[i] != 0) allzero = 0;
        g_is64 = allzero;
    }
}

__device__ __forceinline__ int edge_at(const void* ei, int idx, int is64) {
    return is64 ? (int)((const long long*)ei)[idx] : ((const int*)ei)[idx];
}

// ---------------------------------------------------------------------------
// CSR build
// ---------------------------------------------------------------------------
__global__ void k_zero_deg(int n) {
    int i = blockIdx.x * blockDim.x + threadIdx.x;
    if (i < n) g_deg[i] = 0;
}

__global__ void k_hist(const void* __restrict__ ei, int E) {
    int e = blockIdx.x * blockDim.x + threadIdx.x;
    int is64 = g_is64;
    if (e < E) atomicAdd(&g_deg[edge_at(ei, E + e, is64)], 1);
}

// Phase 1: per-block (1024) scan -> local exclusive + block sums
__global__ void k_scan_local(int n) {
    __shared__ int warp_sums[32];
    int lane = threadIdx.x & 31, wid = threadIdx.x >> 5;
    int i = blockIdx.x * 1024 + threadIdx.x;
    int v = (i < n) ? g_deg[i] : 0;
    int s = v;
    #pragma unroll
    for (int o = 1; o < 32; o <<= 1) {
        int t = __shfl_up_sync(0xFFFFFFFFu, s, o);
        if (lane >= o) s += t;
    }
    if (lane == 31) warp_sums[wid] = s;
    __syncthreads();
    if (wid == 0) {
        int ws = warp_sums[lane];
        #pragma unroll
        for (int o = 1; o < 32; o <<= 1) {
            int t = __shfl_up_sync(0xFFFFFFFFu, ws, o);
            if (lane >= o) ws += t;
        }
        warp_sums[lane] = ws;
    }
    __syncthreads();
    int incl = s + (wid > 0 ? warp_sums[wid - 1] : 0);
    if (i < n) g_off[i] = incl - v;
    if (threadIdx.x == 1023) g_bsum[blockIdx.x] = incl;
}

// Phase 2: one warp scans up to 64 block sums
__global__ void k_scan_mid(int nb, int n) {
    int lane = threadIdx.x;
    int v0 = (lane < nb) ? g_bsum[lane] : 0;
    int v1 = (lane + 32 < nb) ? g_bsum[lane + 32] : 0;
    int s0 = v0;
    #pragma unroll
    for (int o = 1; o < 32; o <<= 1) {
        int t = __shfl_up_sync(0xFFFFFFFFu, s0, o);
        if (lane >= o) s0 += t;
    }
    int tot0 = __shfl_sync(0xFFFFFFFFu, s0, 31);
    int s1 = v1;
    #pragma unroll
    for (int o = 1; o < 32; o <<= 1) {
        int t = __shfl_up_sync(0xFFFFFFFFu, s1, o);
        if (lane >= o) s1 += t;
    }
    s1 += tot0;
    if (lane < nb) g_bpre[lane] = s0 - v0;
    if (lane + 32 < nb) g_bpre[lane + 32] = s1 - v1;
    if (lane == 31) g_off[n] = __shfl_sync(0xFFFFFFFFu, s1, 31);
}

// Phase 3: add block prefix, init cursors
__global__ void k_scan_add(int n) {
    int i = blockIdx.x * 1024 + threadIdx.x;
    if (i < n) {
        int o = g_off[i] + g_bpre[blockIdx.x];
        g_off[i] = o;
        g_cursor[i] = o;
    }
}

__global__ void k_fill(const void* __restrict__ ei, int E) {
    int e = blockIdx.x * blockDim.x + threadIdx.x;
    int is64 = g_is64;
    if (e < E) {
        int s = edge_at(ei, e, is64);
        int d = edge_at(ei, E + e, is64);
        g_esrc[atomicAdd(&g_cursor[d], 1)] = s;
    }
}

// ---------------------------------------------------------------------------
// Aggregation: warp per node, mean over in-neighbors -> g_agg
// ---------------------------------------------------------------------------
__global__ void k_aggregate(const float* __restrict__ xext, int use_h, int n) {
    const float* xin = use_h ? (const float*)g_h : xext;
    int warp = (blockIdx.x * blockDim.x + threadIdx.x) >> 5;
    int lane = threadIdx.x & 31;
    if (warp >= n) return;
    int s0 = g_off[warp];
    int s1 = g_off[warp + 1];
    float4 acc = make_float4(0.f, 0.f, 0.f, 0.f);
    for (int e = s0; e < s1; e++) {
        int src = g_esrc[e];
        float4 v = *(const float4*)(xin + (size_t)src * D + lane * 4);
        acc.x += v.x; acc.y += v.y; acc.z += v.z; acc.w += v.w;
    }
    int cnt = s1 - s0;
    float inv = (cnt > 0) ? (1.0f / (float)cnt) : 0.0f;
    acc.x *= inv; acc.y *= inv; acc.z *= inv; acc.w *= inv;
    *(float4*)(g_agg + (size_t)warp * D + lane * 4) = acc;
}

// ---------------------------------------------------------------------------
// Tensor-core GEMM via mma.sync (bf16, fp32 acc), fp32 emulated with hi/lo
// split: out = [relu]( g_agg @ Wl^T + b + B @ Wr^T ).
// Tile M=128, N=128, K=128, 2 passes sharing accumulators.
// 8 warps in a 4(M) x 2(N) grid: each warp M=32 (2 m16 tiles) x N=64 (8 n8).
// Smem: bf16 hi/lo tiles for A and W, row stride 136 (ldmatrix conflict-free).
// ---------------------------------------------------------------------------
#define SA 136
#define TILE_BYTES (128 * SA * 2)          // 34816
#define OFF_AH 0
#define OFF_AL TILE_BYTES
#define OFF_BH (2 * TILE_BYTES)
#define OFF_BL (3 * TILE_BYTES)
#define GEMM_SMEM (4 * TILE_BYTES)         // 139264

__device__ __forceinline__ void conv_tile(const float* __restrict__ X, int row0, int n,
                                          __nv_bfloat16* __restrict__ Hp,
                                          __nv_bfloat16* __restrict__ Lp,
                                          int tid, bool guard) {
    #pragma unroll
    for (int it = 0; it < 16; it++) {
        int idx = it * 256 + tid;
        int r = idx >> 5, c4 = (idx & 31) * 4;
        int gr = row0 + r;
        float4 v = make_float4(0.f, 0.f, 0.f, 0.f);
        if (!guard || gr < n) v = *(const float4*)(X + (size_t)gr * D + c4);
        __nv_bfloat16 h0 = __float2bfloat16(v.x), h1 = __float2bfloat16(v.y);
        __nv_bfloat16 h2 = __float2bfloat16(v.z), h3 = __float2bfloat16(v.w);
        __nv_bfloat16 l0 = __float2bfloat16(v.x - __bfloat162float(h0));
        __nv_bfloat16 l1 = __float2bfloat16(v.y - __bfloat162float(h1));
        __nv_bfloat16 l2 = __float2bfloat16(v.z - __bfloat162float(h2));
        __nv_bfloat16 l3 = __float2bfloat16(v.w - __bfloat162float(h3));
        __nv_bfloat162 hp0, hp1, lp0, lp1;
        hp0.x = h0; hp0.y = h1; hp1.x = h2; hp1.y = h3;
        lp0.x = l0; lp0.y = l1; lp1.x = l2; lp1.y = l3;
        uint2 hu, lu;
        hu.x = *(uint32_t*)&hp0; hu.y = *(uint32_t*)&hp1;
        lu.x = *(uint32_t*)&lp0; lu.y = *(uint32_t*)&lp1;
        *(uint2*)&Hp[r * SA + c4] = hu;
        *(uint2*)&Lp[r * SA + c4] = lu;
    }
}

template <bool RELU>
__global__ void __launch_bounds__(256)
k_gemm_mma(const float* __restrict__ Bext, int B_is_h,
           const float* __restrict__ Wl, const float* __restrict__ Wr,
           const float* __restrict__ bias,
           float* __restrict__ outext, int out_is_h, int n) {
    extern __shared__ __align__(16) char sm[];
    __nv_bfloat16* AH = (__nv_bfloat16*)(sm + OFF_AH);
    __nv_bfloat16* AL = (__nv_bfloat16*)(sm + OFF_AL);
    __nv_bfloat16* BH = (__nv_bfloat16*)(sm + OFF_BH);
    __nv_bfloat16* BL = (__nv_bfloat16*)(sm + OFF_BL);

    const float* Bp = B_is_h ? (const float*)g_h : Bext;
    float* outp = out_is_h ? (float*)g_h : outext;

    const int tid = threadIdx.x;
    const int wid = tid >> 5;
    const int lane = tid & 31;
    const int warp_m = wid >> 1;      // 0..3 -> rows warp_m*32
    const int warp_n = wid & 1;       // 0..1 -> cols warp_n*64
    const int row0 = blockIdx.x * 128;

    float acc[2][8][4];
    #pragma unroll
    for (int t = 0; t < 2; t++)
        #pragma unroll
        for (int nt = 0; nt < 8; nt++)
            #pragma unroll
            for (int q = 0; q < 4; q++) acc[t][nt][q] = 0.f;

    #pragma unroll
    for (int pass = 0; pass < 2; pass++) {
        const float* X = pass ? Bp : (const float*)g_agg;
        const float* W = pass ? Wr : Wl;

        __syncthreads();   // previous pass's smem reads complete
        conv_tile(X, row0, n, AH, AL, tid, true);
        conv_tile(W, 0, 128, BH, BL, tid, false);
        __syncthreads();

        #pragma unroll
        for (int ks = 0; ks < 8; ks++) {
            const int k0 = ks * 16;
            uint32_t ah[2][4], al[2][4];
            #pragma unroll
            for (int t = 0; t < 2; t++) {
                int mrow = warp_m * 32 + t * 16 + (lane & 15);
                int mcol = k0 + (lane >> 4) * 8;
                LDSM_X4(ah[t][0], ah[t][1], ah[t][2], ah[t][3],
                        smem_u32(&AH[mrow * SA + mcol]));
                LDSM_X4(al[t][0], al[t][1], al[t][2], al[t][3],
                        smem_u32(&AL[mrow * SA + mcol]));
            }
            #pragma unroll
            for (int np = 0; np < 4; np++) {
                int nn = warp_n * 64 + np * 16 + (lane & 7) + ((lane >> 4) << 3);
                int kk = k0 + ((lane >> 3) & 1) * 8;
                uint32_t bh0, bh1, bh2, bh3, bl0, bl1, bl2, bl3;
                LDSM_X4(bh0, bh1, bh2, bh3, smem_u32(&BH[nn * SA + kk]));
                LDSM_X4(bl0, bl1, bl2, bl3, smem_u32(&BL[nn * SA + kk]));
                #pragma unroll
                for (int t = 0; t < 2; t++) {
                    MMA16816(acc[t][np * 2], ah[t], bh0, bh1);
                    MMA16816(acc[t][np * 2], ah[t], bl0, bl1);
                    MMA16816(acc[t][np * 2], al[t], bh0, bh1);
                    MMA16816(acc[t][np * 2 + 1], ah[t], bh2, bh3);
                    MMA16816(acc[t][np * 2 + 1], ah[t], bl2, bl3);
                    MMA16816(acc[t][np * 2 + 1], al[t], bh2, bh3);
                }
            }
        }
    }

    // Epilogue: c0,c1 -> (row, col..col+1); c2,c3 -> (row+8, col..col+1)
    #pragma unroll
    for (int t = 0; t < 2; t++) {
        int rbase = row0 + warp_m * 32 + t * 16 + (lane >> 2);
        #pragma unroll
        for (int nt = 0; nt < 8; nt++) {
            int col = warp_n * 64 + nt * 8 + (lane & 3) * 2;
            float2 bb = *(const float2*)&bias[col];
            if (rbase < n) {
                float2 v;
                v.x = acc[t][nt][0] + bb.x;
                v.y = acc[t][nt][1] + bb.y;
                if (RELU) { v.x = fmaxf(v.x, 0.f); v.y = fmaxf(v.y, 0.f); }
                *(float2*)(outp + (size_t)rbase * D + col) = v;
            }
            if (rbase + 8 < n) {
                float2 v;
                v.x = acc[t][nt][2] + bb.x;
                v.y = acc[t][nt][3] + bb.y;
                if (RELU) { v.x = fmaxf(v.x, 0.f); v.y = fmaxf(v.y, 0.f); }
                *(float2*)(outp + (size_t)(rbase + 8) * D + col) = v;
            }
        }
    }
}

// ---------------------------------------------------------------------------
extern "C" void kernel_launch(void* const* d_in, const int* in_sizes, int n_in,
                              void* d_out, int out_size) {
    const float* x   = (const float*)d_in[0];
    const void*  ei  = d_in[1];
    const float* Wl0 = (const float*)d_in[2];
    const float* bl0 = (const float*)d_in[3];
    const float* Wr0 = (const float*)d_in[4];
    const float* Wl1 = (const float*)d_in[5];
    const float* bl1 = (const float*)d_in[6];
    const float* Wr1 = (const float*)d_in[7];
    float*       out = (float*)d_out;

    const int n = in_sizes[0] / D;
    const int E = in_sizes[1] / 2;
    const int nb = (n + 1023) / 1024;

    static int attr_set = 0;
    if (!attr_set) {
        cudaFuncSetAttribute(k_gemm_mma<true>,
                             cudaFuncAttributeMaxDynamicSharedMemorySize, GEMM_SMEM);
        cudaFuncSetAttribute(k_gemm_mma<false>,
                             cudaFuncAttributeMaxDynamicSharedMemorySize, GEMM_SMEM);
        attr_set = 1;
    }

    // CSR build (graph identical for both layers)
    k_detect<<<1, 32>>>((const int*)ei);
    k_zero_deg<<<(n + 255) / 256, 256>>>(n);
    k_hist<<<(E + 255) / 256, 256>>>(ei, E);
    k_scan_local<<<nb, 1024>>>(n);
    k_scan_mid<<<1, 32>>>(nb, n);
    k_scan_add<<<nb, 1024>>>(n);
    k_fill<<<(E + 255) / 256, 256>>>(ei, E);

    const int agg_blocks  = (n * 32 + 255) / 256;
    const int gemm_blocks = (n + 127) / 128;

    // Layer 0: g_h = relu(agg(x) @ Wl0^T + b0 + x @ Wr0^T)
    k_aggregate<<<agg_blocks, 256>>>(x, 0, n);
    k_gemm_mma<true><<<gemm_blocks, 256, GEMM_SMEM>>>(x, 0, Wl0, Wr0, bl0, nullptr, 1, n);

    // Layer 1: out = agg(g_h) @ Wl1^T + b1 + g_h @ Wr1^T
    k_aggregate<<<agg_blocks, 256>>>(nullptr, 1, n);
    k_gemm_mma<false><<<gemm_blocks, 256, GEMM_SMEM>>>(nullptr, 1, Wl1, Wr1, bl1, out, 0, n);
}